// round 11
// baseline (speedup 1.0000x reference)
#include <cuda_runtime.h>

#define SS 512
#define BB 64
#define HH 8
#define KK 12
#define TT 4096
#define THRESH 4

// partial parities: [quarter][h][s][b] — fully overwritten each call
__device__ unsigned char g_par[4 * HH * SS * BB];
__device__ unsigned int  g_tokbits[SS * 2];     // fully overwritten each call
__device__ unsigned int  g_ctr;                 // zero-init; returns to 0 each call

// ---- kernel 1: bit-pack tokens (S,B) -> 4KB ----
__global__ void __launch_bounds__(128) softram_packtok_kernel(const int* __restrict__ tokens)
{
    const int gwarp = (blockIdx.x * 128 + threadIdx.x) >> 5;   // 0..63
    const int lane  = threadIdx.x & 31;
    #pragma unroll
    for (int m = 0; m < 8; ++m) {
        const int s = gwarp * 8 + m;
        const unsigned lo = __ballot_sync(0xffffffffu, tokens[s * BB + lane] & 1);
        const unsigned hi = __ballot_sync(0xffffffffu, tokens[s * BB + 32 + lane] & 1);
        if (lane == 0) {
            g_tokbits[2 * s]     = lo;
            g_tokbits[2 * s + 1] = hi;
        }
    }
}

// ---- kernel 2: main triangular XOR-gather + fused last-CTA vote ----
__global__ void __launch_bounds__(256, 8) softram_main_kernel(
    const int* __restrict__ conn,     // (H, B, K)
    const float* __restrict__ ram,    // (H, B, T)
    float* __restrict__ out)          // (S*B), idx = s*B+b
{
    const int bid  = blockIdx.x;
    const int hb   = bid >> 1;
    const int h    = hb >> 6;
    const int b    = hb & (BB - 1);
    const int tid  = threadIdx.x;
    const int lane = tid & 31;
    const int t    = tid & 127;                       // row-quad selector
    const int qr   = (bid & 1) * 2 + (tid >> 7);      // j-quarter 0..3 (warp-uniform)

    __shared__ int      sc[KK];
    __shared__ unsigned stok[SS * 2];        // 4KB packed tokens
    __shared__ unsigned sAqq[SS];            // aq_i * 0x10001
    __shared__ unsigned sAkP[SS / 2];        // word p: lo=ak_{2p+1}, hi=ak_{2p}
    __shared__ unsigned sArP[SS / 2 + 1];    // word q: lo=ar_{2q}, hi=ar_{2q+1}
    __shared__ unsigned tbl[(TT / 32) * 32]; // per-lane replicated bit table (16KB)

    if (tid < KK) sc[tid] = conn[hb * KK + tid];
    for (int i = tid; i < SS * 2; i += 256) stok[i] = g_tokbits[i];
    __syncthreads();

    // ---- address components (pure ALU from packed token bits) ----
    for (int s = tid; s < SS; s += 256) {
        unsigned aq = 0, ak = 0, ar = 0;
        #pragma unroll
        for (int k = 0; k < KK; ++k) {
            const int c = sc[k];                       // warp-uniform
            if (c < BB) {
                aq |= ((stok[2 * s + (c >> 5)] >> (c & 31)) & 1u) << k;
            } else if (c < 2 * BB) {
                const int cc = c - BB;
                ak |= ((stok[2 * s + (cc >> 5)] >> (cc & 31)) & 1u) << k;
            } else {
                ar |= (unsigned)((s >> (c - 2 * BB)) & 1) << k;
            }
        }
        sAqq[s] = aq * 0x10001u;
        ((unsigned short*)sAkP)[s ^ 1] = (unsigned short)ak;
        ((unsigned short*)sArP)[s]     = (unsigned short)ar;
    }

    // ---- pack RAM bits into per-lane replicated table (bank = lane) ----
    {
        const float* rp = ram + (size_t)hb * TT;
        for (int tt = tid; tt < TT; tt += 256) {
            const unsigned wv = __ballot_sync(0xffffffffu, rp[tt] > 0.5f);
            tbl[(tt & 0xFE0) + lane] = wv;             // word (t>>5) at its lane column
        }
    }
    __syncthreads();

    const unsigned* tl = tbl + lane;                   // lane-private bank column
    unsigned char* gp  = g_par + ((size_t)(qr * HH + h) * SS) * BB + b;

    // process quad m: rows ia=2m (accA), ib=2m+1 (accB); pairs p in quarter qr of [0,m)
    #pragma unroll
    for (int q = 0; q < 2; ++q) {
        const int m  = q ? (255 - t) : t;
        const int p0 = (m * qr)       >> 2;
        const int p1 = (m * (qr + 1)) >> 2;

        const unsigned aqA = sAqq[2 * m];
        const unsigned aqB = sAqq[2 * m + 1];
        unsigned accA = 0, accB = 0;

        // B_p (row ib, direct): sArP[m-p] = (ar_{2m-2p+1}<<16)|ar_{2m-2p}
        // A_p (row ia) = prmt(B_{p+1}, B_p, 0x5432) = (ar_{2m-2p}<<16)|ar_{2m-2p-1}
        unsigned Bcur = sArP[m - p0];
        #pragma unroll 4
        for (int p = p0; p < p1; ++p) {
            const unsigned pka   = sAkP[p];
            const unsigned Bnext = sArP[m - p - 1];
            const unsigned Ap    = __byte_perm(Bnext, Bcur, 0x5432);
            const unsigned pxA   = pka ^ Ap   ^ aqA;   // lo:(ia,2p+1) hi:(ia,2p)
            const unsigned pxB   = pka ^ Bcur ^ aqB;   // lo:(ib,2p+1) hi:(ib,2p)
            const unsigned xA1   = pxA >> 16;
            const unsigned xB1   = pxB >> 16;
            const unsigned wA0 = tl[pxA & 0xFE0u];
            const unsigned wA1 = tl[xA1 & 0xFE0u];
            const unsigned wB0 = tl[pxB & 0xFE0u];
            const unsigned wB1 = tl[xB1 & 0xFE0u];
            accA ^= __funnelshift_r(wA0, wA0, pxA);    // target bit lands at bit 0
            accA ^= __funnelshift_r(wA1, wA1, xA1);
            accB ^= __funnelshift_r(wB0, wB0, pxB);
            accB ^= __funnelshift_r(wB1, wB1, xB1);
            Bcur = Bnext;
        }

        if (qr == 3) {   // tail: (ia, j=2m) ; (ib, j=2m) ; (ib, j=2m+1)
            const unsigned ak2  = sAkP[m];             // lo=ak_{2m+1}, hi=ak_{2m}
            const unsigned ar01 = sArP[0];             // lo=ar_0, hi=ar_1
            const unsigned xa   = (aqA & 0xFFFFu) ^ (ak2 >> 16) ^ (ar01 & 0xFFFFu);
            const unsigned wa   = tl[xa & 0xFE0u];
            accA ^= __funnelshift_r(wa, wa, xa);
            const unsigned pxT  = ak2 ^ ar01 ^ aqB;    // lo:(ib,2m+1,ar_0) hi:(ib,2m,ar_1)
            const unsigned xT1  = pxT >> 16;
            const unsigned wt0  = tl[pxT & 0xFE0u];
            const unsigned wt1  = tl[xT1 & 0xFE0u];
            accB ^= __funnelshift_r(wt0, wt0, pxT);
            accB ^= __funnelshift_r(wt1, wt1, xT1);
        }

        // every contribution deposits its bit at bit 0 -> parity is acc & 1
        gp[(size_t)(2 * m)     * BB] = (unsigned char)(accA & 1u);
        gp[(size_t)(2 * m + 1) * BB] = (unsigned char)(accB & 1u);
    }

    // ---- fused reduce: last CTA XORs the four quarter-slabs, votes, thresholds ----
    __threadfence();
    __shared__ int slast;
    __syncthreads();
    if (tid == 0) slast = (atomicAdd(&g_ctr, 1u) == (unsigned)(gridDim.x - 1)) ? 1 : 0;
    __syncthreads();
    if (slast) {
        __threadfence();
        const unsigned* pw = (const unsigned*)g_par;
        const int SL = HH * SS * BB / 4;               // u32 words per quarter-slab
        for (int g = tid; g < SS * BB / 4; g += 256) {
            unsigned sum4 = 0;
            #pragma unroll
            for (int hh = 0; hh < HH; ++hh) {
                const int o = hh * (SS * BB / 4) + g;
                sum4 += pw[o] ^ pw[SL + o] ^ pw[2 * SL + o] ^ pw[3 * SL + o];
            }
            float4 o4;
            o4.x = (( sum4        & 0xffu) > THRESH) ? 1.0f : 0.0f;
            o4.y = (((sum4 >> 8)  & 0xffu) > THRESH) ? 1.0f : 0.0f;
            o4.z = (((sum4 >> 16) & 0xffu) > THRESH) ? 1.0f : 0.0f;
            o4.w = (((sum4 >> 24) & 0xffu) > THRESH) ? 1.0f : 0.0f;
            ((float4*)out)[g] = o4;
        }
        if (tid == 0) g_ctr = 0;   // reset for next graph replay
    }
}

extern "C" void kernel_launch(void* const* d_in, const int* in_sizes, int n_in,
                              void* d_out, int out_size)
{
    const int*   tokens = (const int*)d_in[0];
    const int*   conn   = (const int*)d_in[1];
    const float* ram    = (const float*)d_in[2];
    float*       out    = (float*)d_out;

    softram_packtok_kernel<<<16, 128>>>(tokens);
    softram_main_kernel<<<HH * BB * 2, 256>>>(conn, ram, out);
}

// round 12
// speedup vs baseline: 1.6328x; 1.6328x over previous
#include <cuda_runtime.h>

#define SS 512
#define BB 64
#define HH 8
#define KK 12
#define TT 4096
#define NQ 4     // j-quarter CTAs per (h,b)

// bit-packed partial parities: [qr][h][b][plane][word] u32; 128KB, fully overwritten.
__device__ unsigned int g_parbits[NQ * HH * BB * 2 * 8];
__device__ unsigned int g_tokbits[SS * 2];     // fully overwritten each call
__device__ unsigned int g_ctr;                 // zero-init; returns to 0 each call

// ---- kernel 1: bit-pack tokens (S,B) -> 4KB ----
__global__ void __launch_bounds__(128) softram_packtok_kernel(const int* __restrict__ tokens)
{
    const int gwarp = (blockIdx.x * 128 + threadIdx.x) >> 5;   // 0..63
    const int lane  = threadIdx.x & 31;
    #pragma unroll
    for (int m = 0; m < 8; ++m) {
        const int s = gwarp * 8 + m;
        const unsigned lo = __ballot_sync(0xffffffffu, tokens[s * BB + lane] & 1);
        const unsigned hi = __ballot_sync(0xffffffffu, tokens[s * BB + 32 + lane] & 1);
        if (lane == 0) {
            g_tokbits[2 * s]     = lo;
            g_tokbits[2 * s + 1] = hi;
        }
    }
}

__device__ __forceinline__ unsigned maj3(unsigned a, unsigned b, unsigned c) {
    return (a & b) | (c & (a ^ b));
}

// ---- kernel 2: main triangular XOR-gather + fused last-CTA bitsliced vote ----
__global__ void __launch_bounds__(128) softram_main_kernel(
    const int* __restrict__ conn,     // (H, B, K)
    const float* __restrict__ ram,    // (H, B, T)
    float* __restrict__ out)          // (S*B), idx = s*B+b
{
    const int bid  = blockIdx.x;
    const int hb   = bid >> 2;
    const int qr   = bid & 3;                  // j-quarter (CTA-uniform)
    const int h    = hb >> 6;
    const int b    = hb & (BB - 1);
    const int tid  = threadIdx.x;
    const int lane = tid & 31;
    const int wrp  = tid >> 5;

    __shared__ int      sc[KK];
    __shared__ unsigned stok[SS * 2];        // 4KB packed tokens
    __shared__ unsigned sAqq[SS];            // aq_i * 0x10001
    __shared__ unsigned sAkP[SS / 2];        // word p: lo=ak_{2p+1}, hi=ak_{2p}
    __shared__ unsigned sArP[SS / 2 + 1];    // word q: lo=ar_{2q}, hi=ar_{2q+1}
    __shared__ unsigned tbl[(TT / 32) * 32]; // per-lane replicated bit table (16KB)

    if (tid < KK) sc[tid] = conn[hb * KK + tid];
    for (int i = tid; i < SS * 2; i += 128) stok[i] = g_tokbits[i];
    __syncthreads();

    // ---- address components (pure ALU from packed token bits) ----
    for (int s = tid; s < SS; s += 128) {
        unsigned aq = 0, ak = 0, ar = 0;
        #pragma unroll
        for (int k = 0; k < KK; ++k) {
            const int c = sc[k];                       // warp-uniform
            if (c < BB) {
                aq |= ((stok[2 * s + (c >> 5)] >> (c & 31)) & 1u) << k;
            } else if (c < 2 * BB) {
                const int cc = c - BB;
                ak |= ((stok[2 * s + (cc >> 5)] >> (cc & 31)) & 1u) << k;
            } else {
                ar |= (unsigned)((s >> (c - 2 * BB)) & 1) << k;
            }
        }
        sAqq[s] = aq * 0x10001u;
        ((unsigned short*)sAkP)[s ^ 1] = (unsigned short)ak;
        ((unsigned short*)sArP)[s]     = (unsigned short)ar;
    }

    // ---- pack RAM bits into per-lane replicated table (bank = lane) ----
    {
        const float* rp = ram + (size_t)hb * TT;
        for (int tt = tid; tt < TT; tt += 128) {
            const unsigned wv = __ballot_sync(0xffffffffu, rp[tt] > 0.5f);
            tbl[(tt & 0xFE0) + lane] = wv;
        }
    }
    __syncthreads();

    const unsigned* tl = tbl + lane;                   // lane-private bank column
    // base of this (qr,h,b)'s 16 packed words: [plane][w]
    unsigned* gq = g_parbits + (((qr * HH + h) * BB + b) << 4);

    // process quad m: rows ia=2m (accA), ib=2m+1 (accB); pairs p in quarter qr of [0,m)
    #pragma unroll
    for (int q = 0; q < 2; ++q) {
        const int m  = q ? (255 - tid) : tid;
        const int p0 = (m * qr)       >> 2;
        const int p1 = (m * (qr + 1)) >> 2;

        const unsigned aqA = sAqq[2 * m];
        const unsigned aqB = sAqq[2 * m + 1];
        unsigned accA = 0, accB = 0;

        // B_p (row ib, direct): sArP[m-p] = (ar_{2m-2p+1}<<16)|ar_{2m-2p}
        // A_p (row ia) = prmt(B_{p+1}, B_p, 0x5432) = (ar_{2m-2p}<<16)|ar_{2m-2p-1}
        unsigned Bcur = sArP[m - p0];
        #pragma unroll 4
        for (int p = p0; p < p1; ++p) {
            const unsigned pka   = sAkP[p];
            const unsigned Bnext = sArP[m - p - 1];
            const unsigned Ap    = __byte_perm(Bnext, Bcur, 0x5432);
            const unsigned pxA   = pka ^ Ap   ^ aqA;
            const unsigned pxB   = pka ^ Bcur ^ aqB;
            const unsigned xA1   = pxA >> 16;
            const unsigned xB1   = pxB >> 16;
            const unsigned wA0 = tl[pxA & 0xFE0u];
            const unsigned wA1 = tl[xA1 & 0xFE0u];
            const unsigned wB0 = tl[pxB & 0xFE0u];
            const unsigned wB1 = tl[xB1 & 0xFE0u];
            accA ^= __funnelshift_r(wA0, wA0, pxA);    // target bit lands at bit 0
            accA ^= __funnelshift_r(wA1, wA1, xA1);
            accB ^= __funnelshift_r(wB0, wB0, pxB);
            accB ^= __funnelshift_r(wB1, wB1, xB1);
            Bcur = Bnext;
        }

        if (qr == 3) {   // tail: (ia, j=2m) ; (ib, j=2m) ; (ib, j=2m+1)
            const unsigned ak2  = sAkP[m];
            const unsigned ar01 = sArP[0];
            const unsigned xa   = (aqA & 0xFFFFu) ^ (ak2 >> 16) ^ (ar01 & 0xFFFFu);
            const unsigned wa   = tl[xa & 0xFE0u];
            accA ^= __funnelshift_r(wa, wa, xa);
            const unsigned pxT  = ak2 ^ ar01 ^ aqB;
            const unsigned xT1  = pxT >> 16;
            const unsigned wt0  = tl[pxT & 0xFE0u];
            const unsigned wt1  = tl[xT1 & 0xFE0u];
            accB ^= __funnelshift_r(wt0, wt0, pxT);
            accB ^= __funnelshift_r(wt1, wt1, xT1);
        }

        // pack parities across the warp; q=0: word wrp, bit=lane (m=32*wrp+lane)
        //                               q=1: word 7-wrp, bit=31-lane -> brev
        unsigned mA = __ballot_sync(0xffffffffu, accA & 1u);
        unsigned mB = __ballot_sync(0xffffffffu, accB & 1u);
        if (lane == 0) {
            const int wq = q ? (7 - wrp) : wrp;
            gq[wq]     = q ? __brev(mA) : mA;   // plane 0 (even rows)
            gq[8 + wq] = q ? __brev(mB) : mB;   // plane 1 (odd rows)
        }
    }

    // ---- fused reduce: last CTA, bitsliced majority-of-8 over XOR of 4 quarters ----
    __threadfence();
    __shared__ int slast;
    __syncthreads();
    if (tid == 0) slast = (atomicAdd(&g_ctr, 1u) == (unsigned)(gridDim.x - 1)) ? 1 : 0;
    __syncthreads();
    if (slast) {
        __threadfence();
        const unsigned* G = g_parbits;
        // group = (b, plane, w): 64*2*8 = 1024 groups, 32 outputs each
        for (int grp = tid; grp < BB * 2 * 8; grp += 128) {
            const int gb    = grp >> 4;
            const int plane = (grp >> 3) & 1;
            const int w     = grp & 7;
            const int off   = (plane << 3) + w;
            unsigned x[HH];
            #pragma unroll
            for (int hh = 0; hh < HH; ++hh) {
                const int base = ((hh * BB + gb) << 4) + off;
                x[hh] = G[base]
                      ^ G[base + (HH * BB << 4)]
                      ^ G[base + 2 * (HH * BB << 4)]
                      ^ G[base + 3 * (HH * BB << 4)];
            }
            // bitsliced count of 8 bits, mask = (count >= 5)
            const unsigned s1 = x[0] ^ x[1] ^ x[2], c1 = maj3(x[0], x[1], x[2]);
            const unsigned s2 = x[3] ^ x[4] ^ x[5], c2 = maj3(x[3], x[4], x[5]);
            const unsigned s3 = x[6] ^ x[7],        c3 = x[6] & x[7];
            const unsigned ss = s1 ^ s2 ^ s3,  cs = maj3(s1, s2, s3);   // ones, weight-2
            const unsigned sc = c1 ^ c2 ^ c3,  cc = maj3(c1, c2, c3);   // weight-2, weight-4
            const unsigned tsum = cs ^ sc, tcar = cs & sc;              // weight-2, weight-4
            const unsigned c4s  = cc ^ tcar, c8 = cc & tcar;            // weight-4, weight-8
            const unsigned mask = c8 | (c4s & (tsum | ss));
            #pragma unroll
            for (int l = 0; l < 32; ++l) {
                const int s = ((w * 32 + l) << 1) | plane;
                out[s * BB + gb] = (mask >> l) & 1u ? 1.0f : 0.0f;
            }
        }
        if (tid == 0) g_ctr = 0;   // reset for next graph replay
    }
}

extern "C" void kernel_launch(void* const* d_in, const int* in_sizes, int n_in,
                              void* d_out, int out_size)
{
    const int*   tokens = (const int*)d_in[0];
    const int*   conn   = (const int*)d_in[1];
    const float* ram    = (const float*)d_in[2];
    float*       out    = (float*)d_out;

    softram_packtok_kernel<<<16, 128>>>(tokens);
    softram_main_kernel<<<HH * BB * NQ, 128>>>(conn, ram, out);
}

// round 14
// speedup vs baseline: 1.7030x; 1.0430x over previous
#include <cuda_runtime.h>

#define SS 512
#define BB 64
#define HH 8
#define KK 12
#define TT 4096
#define NSL 16                    // j-slices per (h,b)
#define TOTSL (HH * BB * NSL)     // 8192 work items
#define GRID_MAIN 1184            // 148 SMs x 8 resident CTAs -> single wave

// packed parities [h][b][plane][w] (32KB): zeroed by packtok, atomicXor'd by main.
__device__ unsigned int g_parbits[HH * BB * 2 * 8];
__device__ unsigned int g_tokbits[SS * 2];     // fully overwritten each call
__device__ unsigned int g_ctr;                 // zero-init; returns to 0 each call

// ---- kernel 1: bit-pack tokens + zero the parity slab ----
__global__ void __launch_bounds__(128) softram_packtok_kernel(const int* __restrict__ tokens)
{
    const int gtid  = blockIdx.x * 128 + threadIdx.x;
    const int gwarp = gtid >> 5;
    const int lane  = threadIdx.x & 31;
    #pragma unroll
    for (int m = 0; m < 8; ++m) {
        const int s = gwarp * 8 + m;
        const unsigned lo = __ballot_sync(0xffffffffu, tokens[s * BB + lane] & 1);
        const unsigned hi = __ballot_sync(0xffffffffu, tokens[s * BB + 32 + lane] & 1);
        if (lane == 0) {
            g_tokbits[2 * s]     = lo;
            g_tokbits[2 * s + 1] = hi;
        }
    }
    #pragma unroll
    for (int i = gtid; i < HH * BB * 16; i += 16 * 128) g_parbits[i] = 0;
}

__device__ __forceinline__ unsigned maj3(unsigned a, unsigned b, unsigned c) {
    return (a & b) | (c & (a ^ b));
}

// ---- kernel 2: persistent main kernel + fused last-CTA bitsliced vote ----
__global__ void __launch_bounds__(128, 8) softram_main_kernel(
    const int* __restrict__ conn,     // (H, B, K)
    const float* __restrict__ ram,    // (H, B, T)
    float* __restrict__ out)          // (S*B), idx = s*B+b
{
    const int cta  = blockIdx.x;
    const int tid  = threadIdx.x;
    const int lane = tid & 31;
    const int wrp  = tid >> 5;

    __shared__ int      sc[KK];
    __shared__ unsigned sAqq[SS];            // aq_i * 0x10001
    __shared__ unsigned sAkP[SS / 2];        // word p: lo=ak_{2p+1}, hi=ak_{2p}
    __shared__ unsigned sArP[SS / 2 + 1];    // word q: lo=ar_{2q}, hi=ar_{2q+1}
    __shared__ unsigned sbuf[TT / 32 * 32];  // phase1: packed tokens (first 1024); later: bit table (16KB)

    // contiguous item range for this CTA
    const int s0 = (int)(((long long)cta       * TOTSL) / GRID_MAIN);
    const int s1 = (int)(((long long)(cta + 1) * TOTSL) / GRID_MAIN);

    int s = s0;
    while (s < s1) {
        const int hb  = s >> 4;
        const int a   = s & 15;
        const int e16 = min(s1 - (hb << 4), 16);   // merged range [a, e16) within this hb

        // ---- per-hb setup ----
        __syncthreads();                           // protect sbuf/tables from previous iteration's readers
        if (tid < KK) sc[tid] = conn[hb * KK + tid];
        for (int i = tid; i < SS * 2; i += 128) sbuf[i] = g_tokbits[i];
        __syncthreads();

        for (int ss2 = tid; ss2 < SS; ss2 += 128) {
            unsigned aq = 0, ak = 0, ar = 0;
            #pragma unroll
            for (int k = 0; k < KK; ++k) {
                const int c = sc[k];               // warp-uniform
                if (c < BB) {
                    aq |= ((sbuf[2 * ss2 + (c >> 5)] >> (c & 31)) & 1u) << k;
                } else if (c < 2 * BB) {
                    const int cc = c - BB;
                    ak |= ((sbuf[2 * ss2 + (cc >> 5)] >> (cc & 31)) & 1u) << k;
                } else {
                    ar |= (unsigned)((ss2 >> (c - 2 * BB)) & 1) << k;
                }
            }
            sAqq[ss2] = aq * 0x10001u;
            ((unsigned short*)sAkP)[ss2 ^ 1] = (unsigned short)ak;
            ((unsigned short*)sArP)[ss2]     = (unsigned short)ar;
        }
        __syncthreads();                           // all sbuf(token) reads done

        {   // bit table into sbuf (per-lane replicated, bank = lane)
            const float* rp = ram + (size_t)hb * TT;
            for (int tt = tid; tt < TT; tt += 128) {
                const unsigned wv = __ballot_sync(0xffffffffu, rp[tt] > 0.5f);
                sbuf[(tt & 0xFE0) + lane] = wv;
            }
        }
        __syncthreads();

        const unsigned* tl = sbuf + lane;          // lane-private bank column
        unsigned* gq = g_parbits + (hb << 4);      // 16 words: [plane][w]

        // ---- merged inner loop over pairs p in [m*a/16, m*e16/16) ----
        #pragma unroll
        for (int q = 0; q < 2; ++q) {
            const int m  = q ? (255 - tid) : tid;
            const int p0 = (m * a)   >> 4;
            const int p1 = (m * e16) >> 4;

            const unsigned aqA = sAqq[2 * m];
            const unsigned aqB = sAqq[2 * m + 1];
            unsigned accA = 0, accB = 0;

            // B_p (row ib=2m+1, direct): sArP[m-p] = (ar_{2m-2p+1}<<16)|ar_{2m-2p}
            // A_p (row ia=2m) = prmt(B_{p+1}, B_p, 0x5432)
            unsigned Bcur = sArP[m - p0];
            #pragma unroll 4
            for (int p = p0; p < p1; ++p) {
                const unsigned pka   = sAkP[p];
                const unsigned Bnext = sArP[m - p - 1];
                const unsigned Ap    = __byte_perm(Bnext, Bcur, 0x5432);
                const unsigned pxA   = pka ^ Ap   ^ aqA;
                const unsigned pxB   = pka ^ Bcur ^ aqB;
                const unsigned xA1   = pxA >> 16;
                const unsigned xB1   = pxB >> 16;
                const unsigned wA0 = tl[pxA & 0xFE0u];
                const unsigned wA1 = tl[xA1 & 0xFE0u];
                const unsigned wB0 = tl[pxB & 0xFE0u];
                const unsigned wB1 = tl[xB1 & 0xFE0u];
                accA ^= __funnelshift_r(wA0, wA0, pxA);    // target bit lands at bit 0
                accA ^= __funnelshift_r(wA1, wA1, xA1);
                accB ^= __funnelshift_r(wB0, wB0, pxB);
                accB ^= __funnelshift_r(wB1, wB1, xB1);
                Bcur = Bnext;
            }

            if (e16 == 16) {   // tail: (ia, j=2m) ; (ib, j=2m) ; (ib, j=2m+1)
                const unsigned ak2  = sAkP[m];
                const unsigned ar01 = sArP[0];
                const unsigned xa   = (aqA & 0xFFFFu) ^ (ak2 >> 16) ^ (ar01 & 0xFFFFu);
                const unsigned wa   = tl[xa & 0xFE0u];
                accA ^= __funnelshift_r(wa, wa, xa);
                const unsigned pxT  = ak2 ^ ar01 ^ aqB;
                const unsigned xT1  = pxT >> 16;
                const unsigned wt0  = tl[pxT & 0xFE0u];
                const unsigned wt1  = tl[xT1 & 0xFE0u];
                accB ^= __funnelshift_r(wt0, wt0, pxT);
                accB ^= __funnelshift_r(wt1, wt1, xT1);
            }

            // warp-pack parities; q=0: word wrp bit lane; q=1: word 7-wrp bit 31-lane
            const unsigned mA = __ballot_sync(0xffffffffu, accA & 1u);
            const unsigned mB = __ballot_sync(0xffffffffu, accB & 1u);
            if (lane == 0) {
                const int wq = q ? (7 - wrp) : wrp;
                atomicXor(&gq[wq],     q ? __brev(mA) : mA);   // plane 0 (even rows)
                atomicXor(&gq[8 + wq], q ? __brev(mB) : mB);   // plane 1 (odd rows)
            }
        }

        s = (hb << 4) + e16;
    }

    // ---- fused reduce: last CTA, bitsliced majority-of-8 ----
    __threadfence();
    __shared__ int slast;
    __syncthreads();
    if (tid == 0) slast = (atomicAdd(&g_ctr, 1u) == (unsigned)(gridDim.x - 1)) ? 1 : 0;
    __syncthreads();
    if (slast) {
        __threadfence();
        const unsigned* G = g_parbits;
        // group = (b, plane, w): 64*2*8 = 1024 groups, 32 outputs each
        for (int grp = tid; grp < BB * 2 * 8; grp += 128) {
            const int gb    = grp >> 4;
            const int plane = (grp >> 3) & 1;
            const int w     = grp & 7;
            unsigned x[HH];
            #pragma unroll
            for (int hh = 0; hh < HH; ++hh)
                x[hh] = G[(((hh << 6) + gb) << 4) + (plane << 3) + w];
            // bitsliced count of 8 bits, mask = (count >= 5)
            const unsigned s1v = x[0] ^ x[1] ^ x[2], c1 = maj3(x[0], x[1], x[2]);
            const unsigned s2v = x[3] ^ x[4] ^ x[5], c2 = maj3(x[3], x[4], x[5]);
            const unsigned s3v = x[6] ^ x[7],        c3 = x[6] & x[7];
            const unsigned ssv = s1v ^ s2v ^ s3v, cs = maj3(s1v, s2v, s3v);
            const unsigned scv = c1 ^ c2 ^ c3,    cc = maj3(c1, c2, c3);
            const unsigned tsum = cs ^ scv, tcar = cs & scv;
            const unsigned c4s  = cc ^ tcar, c8 = cc & tcar;
            const unsigned mask = c8 | (c4s & (tsum | ssv));
            #pragma unroll
            for (int l = 0; l < 32; ++l) {
                const int srow = ((w * 32 + l) << 1) | plane;
                out[srow * BB + gb] = (mask >> l) & 1u ? 1.0f : 0.0f;
            }
        }
        if (tid == 0) g_ctr = 0;   // reset for next graph replay
    }
}

extern "C" void kernel_launch(void* const* d_in, const int* in_sizes, int n_in,
                              void* d_out, int out_size)
{
    const int*   tokens = (const int*)d_in[0];
    const int*   conn   = (const int*)d_in[1];
    const float* ram    = (const float*)d_in[2];
    float*       out    = (float*)d_out;

    softram_packtok_kernel<<<16, 128>>>(tokens);
    softram_main_kernel<<<GRID_MAIN, 128>>>(conn, ram, out);
}

// round 15
// speedup vs baseline: 1.8379x; 1.0792x over previous
#include <cuda_runtime.h>

#define SS 512
#define BB 64
#define HH 8
#define KK 12
#define TT 4096
#define NHB (HH * BB)
#define RUN 4
#define GRID_MAIN 1184

// packed parities [hb][plane(2)][w(8)] (32KB): zeroed by packtok, XOR'd by main.
__device__ unsigned g_parbits[NHB * 16];
__device__ unsigned g_tokbits[SS * 2];          // fully overwritten each call
__device__ unsigned g_hbinfo[NHB];              // fully overwritten each call
__device__ unsigned short g_fastlist[NHB];      // overwritten (first g_nfast)
__device__ unsigned short g_slowlist[NHB];      // overwritten (first g_nslow)
__device__ unsigned g_nfast, g_nslow;           // overwritten each call
__device__ unsigned g_tick, g_ctr;              // zero-init; reset to 0 by last CTA

// ---- kernel 1: pack tokens, zero parity slab, classify each (h,b) ----
__global__ void __launch_bounds__(128) softram_packtok_kernel(
    const int* __restrict__ tokens, const int* __restrict__ conn)
{
    const int gtid  = blockIdx.x * 128 + threadIdx.x;
    const int gwarp = gtid >> 5;
    const int lane  = threadIdx.x & 31;
    #pragma unroll
    for (int m = 0; m < 8; ++m) {
        const int s = gwarp * 8 + m;
        const unsigned lo = __ballot_sync(0xffffffffu, tokens[s * BB + lane] & 1);
        const unsigned hi = __ballot_sync(0xffffffffu, tokens[s * BB + 32 + lane] & 1);
        if (lane == 0) { g_tokbits[2 * s] = lo; g_tokbits[2 * s + 1] = hi; }
    }
    #pragma unroll
    for (int i = gtid; i < NHB * 16; i += 16 * 128) g_parbits[i] = 0;

    if (gtid < NHB) {
        unsigned qm = 0, km = 0; int nr = 0;
        #pragma unroll
        for (int k = 0; k < KK; ++k) {
            const int c = conn[gtid * KK + k];
            if (c < BB) qm |= 1u << k;
            else if (c < 2 * BB) km |= 1u << k;
            else ++nr;
        }
        const int nq = __popc(qm);
        const unsigned fast = (nr == 0 && nq >= 1 && nq <= 7) ? 1u : 0u;
        g_hbinfo[gtid] = qm | (km << 12) | ((unsigned)nq << 24) | (fast << 28);
    }
}

// ---- kernel 2: compact fast/slow lists (1 warp) ----
__global__ void softram_compact_kernel()
{
    const int lane = threadIdx.x;
    int nf = 0, ns = 0;
    for (int gblk = 0; gblk < 16; ++gblk) {
        const int hb = gblk * 32 + lane;
        const unsigned f  = (g_hbinfo[hb] >> 28) & 1u;
        const unsigned mf = __ballot_sync(0xffffffffu, f);
        const unsigned lt = (lane == 0) ? 0u : ((1u << lane) - 1u);
        if (f) g_fastlist[nf + __popc(mf & lt)] = (unsigned short)hb;
        else   g_slowlist[ns + __popc(~mf & lt)] = (unsigned short)hb;
        nf += __popc(mf);
        ns += 32 - __popc(mf);
    }
    if (lane == 0) { g_nfast = (unsigned)nf; g_nslow = (unsigned)ns; }
}

__device__ __forceinline__ unsigned maj3(unsigned a, unsigned b, unsigned c) {
    return (a & b) | (c & (a ^ b));
}

// ---- kernel 3: persistent ticketed main + fused last-CTA bitsliced vote ----
__global__ void __launch_bounds__(128) softram_main_kernel(
    const int* __restrict__ conn,     // (H, B, K)
    const float* __restrict__ ram,    // (H, B, T)
    float* __restrict__ out)          // (S*B), idx = s*B+b
{
    const int tid  = threadIdx.x;
    const int lane = tid & 31;
    const int wrp  = tid >> 5;

    __shared__ int      sc[KK];
    __shared__ unsigned sAqq[SS];            // slow: aq*0x10001
    __shared__ unsigned sAkP[SS / 2];        // slow: word p: lo=ak_{2p+1}, hi=ak_{2p}
    __shared__ unsigned sArP[SS / 2 + 1];    // slow: word q: lo=ar_{2q}, hi=ar_{2q+1}
    __shared__ unsigned sbuf[TT / 32 * 32];  // tokens / bit table / ST (16KB)
    __shared__ unsigned short sck[SS];       // fast: compressed Ak
    __shared__ unsigned char  scq[SS];       // fast: compressed Aq
    __shared__ unsigned char  spar[SS];      // fast: per-row parity staging
    __shared__ unsigned swsum[4][4];         // fast: warp scan totals
    __shared__ int sticket;

    const int nf     = (int)g_nfast;
    const int ns     = (int)g_nslow;
    const int nunits = nf + 4 * ns;          // 16 slices / RUN=4 per slow hb

    for (;;) {
        __syncthreads();
        if (tid == 0) sticket = (int)atomicAdd(&g_tick, 1u);
        __syncthreads();
        const int u = sticket;
        if (u >= nunits) break;

        if (u < nf) {
            // ================= FAST PATH (nr==0, 1<=nq<=7) =================
            const int hb = g_fastlist[u];
            const unsigned info = g_hbinfo[hb];
            const unsigned qm = info & 0xFFFu;
            const unsigned km = (info >> 12) & 0xFFFu;
            const int nq = (int)((info >> 24) & 0xFu);
            const int nk = KK - nq;
            const int w_pad = 1 << ((nq > 5) ? (nq - 5) : 0);

            if (tid < KK) sc[tid] = conn[hb * KK + tid];
            for (int i = tid; i < SS * 2; i += 128) sbuf[i] = g_tokbits[i];
            __syncthreads();

            // compressed address components
            for (int s = tid; s < SS; s += 128) {
                unsigned cq = 0, ck = 0;
                #pragma unroll
                for (int k = 0; k < KK; ++k) {
                    const int c = sc[k];
                    if (c < BB) {
                        const unsigned bit = (sbuf[2 * s + (c >> 5)] >> (c & 31)) & 1u;
                        cq |= bit << __popc(qm & ((1u << k) - 1u));
                    } else {    // k-class (nr==0 guarantees no r)
                        const int cc = c - BB;
                        const unsigned bit = (sbuf[2 * s + (cc >> 5)] >> (cc & 31)) & 1u;
                        ck |= bit << __popc(km & ((1u << k) - 1u));
                    }
                }
                scq[s] = (unsigned char)cq;
                sck[s] = (unsigned short)ck;
            }
            __syncthreads();

            // raw table bits -> sbuf[0..128)
            {
                const float* rp = ram + (size_t)hb * TT;
                for (int t2 = tid; t2 < TT; t2 += 128) {
                    const unsigned wv = __ballot_sync(0xffffffffu, rp[t2] > 0.5f);
                    if (lane == 0) sbuf[t2 >> 5] = wv;
                }
            }
            __syncthreads();

            // permuted table ST[ck] (bitvector over cq) at sbuf[128 + ck*w_pad]
            for (int ck = tid; ck < (1 << nk); ck += 128) {
                unsigned tk = 0;
                {   unsigned tmp = (unsigned)ck;
                    #pragma unroll
                    for (int k = 0; k < KK; ++k)
                        if ((km >> k) & 1u) { if (tmp & 1u) tk |= 1u << k; tmp >>= 1; }
                }
                unsigned acc = 0, tq = 0;
                const int NQ2 = 1 << nq;
                for (int cq = 0; cq < NQ2; ++cq) {
                    const unsigned t = tk | tq;
                    acc |= ((sbuf[t >> 5] >> (t & 31)) & 1u) << (cq & 31);
                    if ((cq & 31) == 31) { sbuf[128 + ck * w_pad + (cq >> 5)] = acc; acc = 0; }
                    tq = (tq - qm) & qm;
                }
                if (nq < 5) sbuf[128 + ck * w_pad] = acc;
            }
            __syncthreads();

            // XOR prefix scan of ST[ck_j]; thread owns j/rows [4t, 4t+4)
            const int jb = tid * 4;
            unsigned v0 = 0, v1 = 0, v2 = 0, v3 = 0;
            #pragma unroll
            for (int uu = 0; uu < 4; ++uu) {
                const int base = 128 + (int)sck[jb + uu] * w_pad;
                v0 ^= sbuf[base]; v1 ^= sbuf[base + 1];
                v2 ^= sbuf[base + 2]; v3 ^= sbuf[base + 3];
            }
            unsigned i0 = v0, i1 = v1, i2 = v2, i3 = v3;
            #pragma unroll
            for (int off = 1; off < 32; off <<= 1) {
                const unsigned o0 = __shfl_up_sync(0xffffffffu, i0, off);
                const unsigned o1 = __shfl_up_sync(0xffffffffu, i1, off);
                const unsigned o2 = __shfl_up_sync(0xffffffffu, i2, off);
                const unsigned o3 = __shfl_up_sync(0xffffffffu, i3, off);
                if (lane >= off) { i0 ^= o0; i1 ^= o1; i2 ^= o2; i3 ^= o3; }
            }
            if (lane == 31) { swsum[wrp][0] = i0; swsum[wrp][1] = i1;
                              swsum[wrp][2] = i2; swsum[wrp][3] = i3; }
            __syncthreads();
            unsigned e0 = i0 ^ v0, e1 = i1 ^ v1, e2 = i2 ^ v2, e3 = i3 ^ v3;  // warp-exclusive
            for (int ww = 0; ww < wrp; ++ww) {
                e0 ^= swsum[ww][0]; e1 ^= swsum[ww][1];
                e2 ^= swsum[ww][2]; e3 ^= swsum[ww][3];
            }
            // rows: include own j's one at a time, extract bit cq_i
            #pragma unroll
            for (int uu = 0; uu < 4; ++uu) {
                const int i = jb + uu;
                const int base = 128 + (int)sck[i] * w_pad;
                e0 ^= sbuf[base]; e1 ^= sbuf[base + 1];
                e2 ^= sbuf[base + 2]; e3 ^= sbuf[base + 3];
                const int cq = (int)scq[i];
                const unsigned sel = (cq & 32) ? ((cq & 64) ? e3 : e1)
                                               : ((cq & 64) ? e2 : e0);
                spar[i] = (unsigned char)((sel >> (cq & 31)) & 1u);
            }
            __syncthreads();
            // pack to g_parbits (plane p word w: bit l = row 64w+2l+p)
            {
                unsigned* gq = g_parbits + hb * 16;
                for (int idx = wrp; idx < 16; idx += 4) {
                    const int p = idx >> 3, w2 = idx & 7;
                    const unsigned mbit =
                        __ballot_sync(0xffffffffu, spar[64 * w2 + 2 * lane + p]);
                    if (lane == 0) gq[(p << 3) + w2] = mbit;
                }
            }
        } else {
            // ================= SLOW PATH: run of RUN slices =================
            int g = (u - nf) * RUN;
            const int gend = g + RUN;
            while (g < gend) {
                const int hb  = g_slowlist[g >> 4];
                const int a   = g & 15;
                const int e16 = min(gend - (g & ~15), 16);

                __syncthreads();
                if (tid < KK) sc[tid] = conn[hb * KK + tid];
                for (int i = tid; i < SS * 2; i += 128) sbuf[i] = g_tokbits[i];
                __syncthreads();

                for (int ss2 = tid; ss2 < SS; ss2 += 128) {
                    unsigned aq = 0, ak = 0, ar = 0;
                    #pragma unroll
                    for (int k = 0; k < KK; ++k) {
                        const int c = sc[k];
                        if (c < BB) {
                            aq |= ((sbuf[2 * ss2 + (c >> 5)] >> (c & 31)) & 1u) << k;
                        } else if (c < 2 * BB) {
                            const int cc = c - BB;
                            ak |= ((sbuf[2 * ss2 + (cc >> 5)] >> (cc & 31)) & 1u) << k;
                        } else {
                            ar |= (unsigned)((ss2 >> (c - 2 * BB)) & 1) << k;
                        }
                    }
                    sAqq[ss2] = aq * 0x10001u;
                    ((unsigned short*)sAkP)[ss2 ^ 1] = (unsigned short)ak;
                    ((unsigned short*)sArP)[ss2]     = (unsigned short)ar;
                }
                __syncthreads();

                {   // per-lane replicated bit table (bank = lane)
                    const float* rp = ram + (size_t)hb * TT;
                    for (int tt = tid; tt < TT; tt += 128) {
                        const unsigned wv = __ballot_sync(0xffffffffu, rp[tt] > 0.5f);
                        sbuf[(tt & 0xFE0) + lane] = wv;
                    }
                }
                __syncthreads();

                const unsigned* tl = sbuf + lane;
                unsigned* gq = g_parbits + (hb << 4);

                #pragma unroll
                for (int q = 0; q < 2; ++q) {
                    const int m  = q ? (255 - tid) : tid;
                    const int p0 = (m * a)   >> 4;
                    const int p1 = (m * e16) >> 4;

                    const unsigned aqA = sAqq[2 * m];
                    const unsigned aqB = sAqq[2 * m + 1];
                    unsigned accA = 0, accB = 0;

                    unsigned Bcur = sArP[m - p0];
                    #pragma unroll 4
                    for (int p = p0; p < p1; ++p) {
                        const unsigned pka   = sAkP[p];
                        const unsigned Bnext = sArP[m - p - 1];
                        const unsigned Ap    = __byte_perm(Bnext, Bcur, 0x5432);
                        const unsigned pxA   = pka ^ Ap   ^ aqA;
                        const unsigned pxB   = pka ^ Bcur ^ aqB;
                        const unsigned xA1   = pxA >> 16;
                        const unsigned xB1   = pxB >> 16;
                        const unsigned wA0 = tl[pxA & 0xFE0u];
                        const unsigned wA1 = tl[xA1 & 0xFE0u];
                        const unsigned wB0 = tl[pxB & 0xFE0u];
                        const unsigned wB1 = tl[xB1 & 0xFE0u];
                        accA ^= __funnelshift_r(wA0, wA0, pxA);
                        accA ^= __funnelshift_r(wA1, wA1, xA1);
                        accB ^= __funnelshift_r(wB0, wB0, pxB);
                        accB ^= __funnelshift_r(wB1, wB1, xB1);
                        Bcur = Bnext;
                    }

                    if (e16 == 16) {   // tail lookups
                        const unsigned ak2  = sAkP[m];
                        const unsigned ar01 = sArP[0];
                        const unsigned xa   = (aqA & 0xFFFFu) ^ (ak2 >> 16) ^ (ar01 & 0xFFFFu);
                        const unsigned wa   = tl[xa & 0xFE0u];
                        accA ^= __funnelshift_r(wa, wa, xa);
                        const unsigned pxT  = ak2 ^ ar01 ^ aqB;
                        const unsigned xT1  = pxT >> 16;
                        const unsigned wt0  = tl[pxT & 0xFE0u];
                        const unsigned wt1  = tl[xT1 & 0xFE0u];
                        accB ^= __funnelshift_r(wt0, wt0, pxT);
                        accB ^= __funnelshift_r(wt1, wt1, xT1);
                    }

                    const unsigned mA = __ballot_sync(0xffffffffu, accA & 1u);
                    const unsigned mB = __ballot_sync(0xffffffffu, accB & 1u);
                    if (lane == 0) {
                        const int wq = q ? (7 - wrp) : wrp;
                        atomicXor(&gq[wq],     q ? __brev(mA) : mA);
                        atomicXor(&gq[8 + wq], q ? __brev(mB) : mB);
                    }
                }
                g = (g & ~15) + e16;
            }
        }
    }

    // ---- fused reduce: last CTA, bitsliced majority-of-8 ----
    __threadfence();
    __shared__ int slast;
    __syncthreads();
    if (tid == 0) slast = (atomicAdd(&g_ctr, 1u) == (unsigned)(gridDim.x - 1)) ? 1 : 0;
    __syncthreads();
    if (slast) {
        __threadfence();
        const unsigned* G = g_parbits;
        for (int grp = tid; grp < BB * 2 * 8; grp += 128) {
            const int gb    = grp >> 4;
            const int plane = (grp >> 3) & 1;
            const int w     = grp & 7;
            unsigned x[HH];
            #pragma unroll
            for (int hh = 0; hh < HH; ++hh)
                x[hh] = G[(((hh << 6) + gb) << 4) + (plane << 3) + w];
            const unsigned s1v = x[0] ^ x[1] ^ x[2], c1 = maj3(x[0], x[1], x[2]);
            const unsigned s2v = x[3] ^ x[4] ^ x[5], c2 = maj3(x[3], x[4], x[5]);
            const unsigned s3v = x[6] ^ x[7],        c3 = x[6] & x[7];
            const unsigned ssv = s1v ^ s2v ^ s3v, cs = maj3(s1v, s2v, s3v);
            const unsigned scv = c1 ^ c2 ^ c3,    cc = maj3(c1, c2, c3);
            const unsigned tsum = cs ^ scv, tcar = cs & scv;
            const unsigned c4s  = cc ^ tcar, c8 = cc & tcar;
            const unsigned mask = c8 | (c4s & (tsum | ssv));
            #pragma unroll
            for (int l = 0; l < 32; ++l) {
                const int srow = ((w * 32 + l) << 1) | plane;
                out[srow * BB + gb] = (mask >> l) & 1u ? 1.0f : 0.0f;
            }
        }
        if (tid == 0) { g_ctr = 0; g_tick = 0; }   // reset for next graph replay
    }
}

extern "C" void kernel_launch(void* const* d_in, const int* in_sizes, int n_in,
                              void* d_out, int out_size)
{
    const int*   tokens = (const int*)d_in[0];
    const int*   conn   = (const int*)d_in[1];
    const float* ram    = (const float*)d_in[2];
    float*       out    = (float*)d_out;

    softram_packtok_kernel<<<16, 128>>>(tokens, conn);
    softram_compact_kernel<<<1, 32>>>();
    softram_main_kernel<<<GRID_MAIN, 128>>>(conn, ram, out);
}